// round 16
// baseline (speedup 1.0000x reference)
#include <cuda_runtime.h>
#include <cstdint>

// SpatialTransformer bilinear flow warp — R5 skeleton + L1-bypass flow loads.
// src:  [B,H,W,1] f32,  flow: [B,H,W,2] f32,  out: [B,H,W,1] f32
// B=32, H=768, W=768.
//
// Proven operating point (R5/R15, 67.9us): 128-thr blocks, 32x16 tile,
// lane -> 32 consecutive x, warp -> 4-row strip, scalar __ldg gathers.
// Single isolated change: flow loads use __ldcg (L2-only, no L1 allocate).
// Rationale: flow streams 151MB through L1 (228KB) and evicts the src
// gather lines (~50KB/SM working set) that the layout relies on for reuse.
// R11's regression bundled evict-first hints WITH a pipelining restructure;
// this isolates the cache-policy lever in its correct (no-allocate) form.

#define BB 32
#define HH 768
#define WW 768
#define HW (HH * WW)

__global__ __launch_bounds__(128) void warp_kernel(
    const float* __restrict__ src,
    const float* __restrict__ flow,
    float* __restrict__ out)
{
    const int tx = threadIdx.x;
    const int xg = blockIdx.x * 32 + (tx & 31);       // global x
    const int yb = blockIdx.y * 16 + (tx >> 5) * 4;   // first of 4 rows
    const int b  = blockIdx.z;

    const float* img = src + b * HW;
    const float  xgf = (float)xg;

    #pragma unroll
    for (int r = 0; r < 4; r++) {
        const int y   = yb + r;
        const int pix = (b * HH + y) * WW + xg;

        // flow: streaming, zero reuse -> bypass L1 allocate (L2 only)
        const float2 f = __ldcg(reinterpret_cast<const float2*>(
                              flow + (size_t)pix * 2));

        const float gx = xgf + f.x;
        const float gy = (float)y + f.y;

        const float x0f = floorf(gx);
        const float y0f = floorf(gy);
        const float x1f = x0f + 1.0f;
        const float y1f = y0f + 1.0f;

        // bilinear weights from UNCLIPPED corners (matches reference)
        const float dx1 = x1f - gx;
        const float dx0 = gx - x0f;
        const float dy1 = y1f - gy;
        const float dy0 = gy - y0f;

        const float wa = dx1 * dy1;
        const float wb = dx0 * dy1;
        const float wc = dx1 * dy0;
        const float wd = dx0 * dy0;

        // clipped integer indices (exact reference semantics)
        const int xi0 = (int)fminf(fmaxf(x0f, 0.0f), (float)(WW - 1));
        const int xi1 = (int)fminf(fmaxf(x1f, 0.0f), (float)(WW - 1));
        const int yi0 = (int)fminf(fmaxf(y0f, 0.0f), (float)(HH - 1));
        const int yi1 = (int)fminf(fmaxf(y1f, 0.0f), (float)(HH - 1));

        const int r0 = yi0 * WW;
        const int r1 = yi1 * WW;

        const float va = __ldg(img + r0 + xi0);
        const float vb = __ldg(img + r0 + xi1);
        const float vc = __ldg(img + r1 + xi0);
        const float vd = __ldg(img + r1 + xi1);

        out[pix] = wa * va + wb * vb + wc * vc + wd * vd;
    }
}

extern "C" void kernel_launch(void* const* d_in, const int* in_sizes, int n_in,
                              void* d_out, int out_size)
{
    const float* src  = (const float*)d_in[0];
    const float* flow = (const float*)d_in[1];
    float* out = (float*)d_out;

    dim3 grid(WW / 32, HH / 16, BB);   // (24, 48, 32)
    warp_kernel<<<grid, 128>>>(src, flow, out);
}

// round 17
// speedup vs baseline: 1.1192x; 1.1192x over previous
#include <cuda_runtime.h>
#include <cstdint>

// SpatialTransformer bilinear flow warp — FINAL (measured-best, benched 2x).
// src:  [B,H,W,1] f32,  flow: [B,H,W,2] f32,  out: [B,H,W,1] f32
// B=32, H=768, W=768.
//
// Operating point established over 12 variants (100.8us -> 67.9us):
//   - 128-thread blocks (4 warps), 32x16 pixel tile, ~90% occupancy, 32 regs
//   - lane -> 32 consecutive x  => flow/out fully coalesced; gathers span
//     minimal x-lines per warp
//   - warp -> 4-row vertical strip => bilinear row-halo reuse in L1
//   - plain scalar __ldg gathers, default cache policy: L1tex wavefront cost
//     is per line-visit; wide/predicated/bypass/smem variants all slower.
// Structural limit: random per-lane flow.y forces ~10 distinct line-visits
// per gather wavefront; cycle model reproduces the 64-68us plateau. DRAM
// traffic is at the mandatory ~300MB floor.

#define BB 32
#define HH 768
#define WW 768
#define HW (HH * WW)

__global__ __launch_bounds__(128) void warp_kernel(
    const float* __restrict__ src,
    const float* __restrict__ flow,
    float* __restrict__ out)
{
    const int tx = threadIdx.x;
    const int xg = blockIdx.x * 32 + (tx & 31);       // global x
    const int yb = blockIdx.y * 16 + (tx >> 5) * 4;   // first of 4 rows
    const int b  = blockIdx.z;

    const float* img = src + b * HW;
    const float  xgf = (float)xg;

    #pragma unroll
    for (int r = 0; r < 4; r++) {
        const int y   = yb + r;
        const int pix = (b * HH + y) * WW + xg;

        const float2 f = *reinterpret_cast<const float2*>(flow + (size_t)pix * 2);

        const float gx = xgf + f.x;
        const float gy = (float)y + f.y;

        const float x0f = floorf(gx);
        const float y0f = floorf(gy);
        const float x1f = x0f + 1.0f;
        const float y1f = y0f + 1.0f;

        // bilinear weights from UNCLIPPED corners (matches reference)
        const float dx1 = x1f - gx;
        const float dx0 = gx - x0f;
        const float dy1 = y1f - gy;
        const float dy0 = gy - y0f;

        const float wa = dx1 * dy1;
        const float wb = dx0 * dy1;
        const float wc = dx1 * dy0;
        const float wd = dx0 * dy0;

        // clipped integer indices (exact reference semantics)
        const int xi0 = (int)fminf(fmaxf(x0f, 0.0f), (float)(WW - 1));
        const int xi1 = (int)fminf(fmaxf(x1f, 0.0f), (float)(WW - 1));
        const int yi0 = (int)fminf(fmaxf(y0f, 0.0f), (float)(HH - 1));
        const int yi1 = (int)fminf(fmaxf(y1f, 0.0f), (float)(HH - 1));

        const int r0 = yi0 * WW;
        const int r1 = yi1 * WW;

        const float va = __ldg(img + r0 + xi0);
        const float vb = __ldg(img + r0 + xi1);
        const float vc = __ldg(img + r1 + xi0);
        const float vd = __ldg(img + r1 + xi1);

        out[pix] = wa * va + wb * vb + wc * vc + wd * vd;
    }
}

extern "C" void kernel_launch(void* const* d_in, const int* in_sizes, int n_in,
                              void* d_out, int out_size)
{
    const float* src  = (const float*)d_in[0];
    const float* flow = (const float*)d_in[1];
    float* out = (float*)d_out;

    dim3 grid(WW / 32, HH / 16, BB);   // (24, 48, 32)
    warp_kernel<<<grid, 128>>>(src, flow, out);
}